// round 17
// baseline (speedup 1.0000x reference)
#include <cuda_runtime.h>
#include <cstdint>

#define NN 20000

// ---------------- device scratch ----------------
__device__ float g_z1 [NN * 64];
__device__ float g_hd1[NN * 64];
__device__ float g_zc [NN * 64];
__device__ float g_u  [NN * 64];

// ---------------- helpers ----------------
__device__ __forceinline__ float warpSumAll(float v) {
#pragma unroll
    for (int o = 16; o > 0; o >>= 1) v += __shfl_xor_sync(0xffffffffu, v, o);
    return v;
}
__device__ __forceinline__ float lrelu(float x) { return x > 0.f ? x : 0.01f * x; }
__device__ __forceinline__ float eluf(float x) {
    if (x > 0.f) return x;
    if (x > -0.25f)
        return x * (1.f + x * (0.5f + x * (0.16666667f + x * 0.041666667f)));
    return __expf(x) - 1.f;
}

union F2U { float2 f; unsigned long long u; };
__device__ __forceinline__ void fma2(float2& c, float2 a, float2 b) {
    F2U A, B, C; A.f = a; B.f = b; C.f = c;
    asm("fma.rn.f32x2 %0, %1, %2, %0;" : "+l"(C.u) : "l"(A.u), "l"(B.u));
    c = C.f;
}

__device__ __forceinline__ void cpasync16(uint32_t dst, const void* src) {
    asm volatile("cp.async.ca.shared.global [%0], [%1], 16;" :: "r"(dst), "l"(src));
}
__device__ __forceinline__ void cp_commit() {
    asm volatile("cp.async.commit_group;" ::: "memory");
}
template <int N>
__device__ __forceinline__ void cp_wait() {
    asm volatile("cp.async.wait_group %0;" :: "n"(N) : "memory");
}

// =====================================================================
// GEMM: 96x64 tile, 384 thr, grid (209,2), 3 blocks/SM one wave.
// K in 4 chunks of 32 (HALVED barrier count vs R13), 2-stage cp.async ring.
// =====================================================================
static constexpr int MT     = 96;
static constexpr int NTHR   = 384;
static constexpr int BPITCH = 68;
static constexpr int APITCH = 36;                 // 32 k + 4 pad
static constexpr int BS_ELEMS = 128 * BPITCH;     // 8704
static constexpr int ASTG_ELEMS = MT * APITCH;    // 3456
static constexpr int GSMEM = (BS_ELEMS + 2 * ASTG_ELEMS) * 4;  // 62464 B

template <int DEC>
__device__ __forceinline__ const float* srcA(const float* __restrict__ Ain, int node, int kg) {
    if (DEC) return (kg < 64) ? (g_zc + node * 64 + kg) : (g_u + node * 64 + kg - 64);
    return Ain + node * 128 + kg;
}

template <int DEC>
__global__ __launch_bounds__(NTHR, 3)
void gemm_f32(const float* __restrict__ Ain, const float* __restrict__ W0,
              const float* __restrict__ W1, float* __restrict__ Oout) {
    extern __shared__ __align__(16) float smem[];
    float* Bs = smem;                            // [128][BPITCH]
    float* As = smem + BS_ELEMS;                 // 2 x [MT][APITCH]

    const int t = threadIdx.x;
    const int tx = t & 15, ty = t >> 4;
    const int node0 = blockIdx.x * MT;
    const int half  = blockIdx.y;
    const int c0 = 4 * tx;

    // cp.async: 2 segs/thread/chunk (768 segs = 96 rows x 8)
    const int r0 = t >> 3,          s0 = t & 7;          // seg t
    const int r1 = (t + 384) >> 3,  s1 = (t + 384) & 7;  // seg t+384
    const int n0g = min(node0 + r0, NN - 1);
    const int n1g = min(node0 + r1, NN - 1);
    const uint32_t abase = (uint32_t)__cvta_generic_to_shared(As);
    const uint32_t d0 = abase + (r0 * APITCH + s0 * 4) * 4;
    const uint32_t d1 = abase + (r1 * APITCH + s1 * 4) * 4;

    // ---- stage W half once ----
    for (int i = t; i < 64 * 128; i += NTHR) {
        const int n = i >> 7, k = i & 127;
        float v;
        if (DEC) v = (k < 64) ? W0[(half * 64 + n) * 64 + k]
                              : W1[(half * 64 + n) * 64 + k - 64];
        else     v = half ? W1[n * 128 + k] : W0[n * 128 + k];
        Bs[k * BPITCH + n] = v;
    }

    // ---- prologue: issue A chunk 0 ----
    cpasync16(d0, srcA<DEC>(Ain, n0g, s0 * 4));
    cpasync16(d1, srcA<DEC>(Ain, n1g, s1 * 4));
    cp_commit();

    float2 acc[4][2];
#pragma unroll
    for (int i = 0; i < 4; i++) { acc[i][0] = make_float2(0.f, 0.f); acc[i][1] = make_float2(0.f, 0.f); }

#pragma unroll 1
    for (int ch = 0; ch < 4; ch++) {
        // issue next chunk into the other stage (its old data consumed last iter)
        if (ch < 3) {
            const uint32_t soff = ((ch + 1) & 1) * ASTG_ELEMS * 4;
            cpasync16(d0 + soff, srcA<DEC>(Ain, n0g, (ch + 1) * 32 + s0 * 4));
            cpasync16(d1 + soff, srcA<DEC>(Ain, n1g, (ch + 1) * 32 + s1 * 4));
            cp_commit();
            cp_wait<1>();
        } else {
            cp_wait<0>();
        }
        __syncthreads();

        const float* Ast = As + (ch & 1) * ASTG_ELEMS;
        const float* Bb  = Bs + ch * 32 * BPITCH;
#pragma unroll
        for (int k4 = 0; k4 < 32; k4 += 4) {
            float a[4][4];
#pragma unroll
            for (int i = 0; i < 4; i++)
                *(float4*)a[i] = *(const float4*)&Ast[(4 * ty + i) * APITCH + k4];
#pragma unroll
            for (int kk = 0; kk < 4; kk++) {
                const float4 bv = *(const float4*)&Bb[(k4 + kk) * BPITCH + c0];
                const float2 b0 = make_float2(bv.x, bv.y);
                const float2 b1 = make_float2(bv.z, bv.w);
#pragma unroll
                for (int i = 0; i < 4; i++) {
                    const float2 av = make_float2(a[i][kk], a[i][kk]);
                    fma2(acc[i][0], av, b0);
                    fma2(acc[i][1], av, b1);
                }
            }
        }
        if (ch < 3) __syncthreads();   // all done with this stage before its reuse next iter
    }

#pragma unroll
    for (int i = 0; i < 4; i++) {
        const int node = node0 + 4 * ty + i;
        if (node >= NN) break;
        const float4 v = make_float4(acc[i][0].x, acc[i][0].y, acc[i][1].x, acc[i][1].y);
        if (DEC) {
            *(float4*)(Oout + node * 128 + half * 64 + c0) = v;
        } else {
            float* dst = half ? g_hd1 : g_z1;
            *(float4*)(dst + node * 64 + c0) = v;
        }
    }
}

// =====================================================================
// encoder aggregation: 64 nodes/block (grid 313), lane-parallel softmax.
// =====================================================================
__global__ __launch_bounds__(256) void enc_agg(const float* __restrict__ attE,
                                               const float* __restrict__ attC) {
    __shared__ __align__(16) float hdT[88][66];
    __shared__ float sT[88];
    __shared__ __align__(16) float wS[3][25][72];
    __shared__ float sAe[64], sAc[64];

    const int t = threadIdx.x, w = t >> 5, lane = t & 31;
    const int nodeBase = blockIdx.x * 64;
    const int nl0 = w * 8;

    if (t < 64) { sAe[t] = attE[t]; sAc[t] = attC[t]; }

    for (int r = w; r < 88; r += 8) {
        int g = nodeBase - 24 + r;
        if (g < 0) g += NN; else if (g >= NN) g -= NN;
        ((float2*)hdT[r])[lane] = ((const float2*)(g_hd1 + g * 64))[lane];
    }
    __syncthreads();

    for (int r = w; r < 88; r += 8) {
        float2 hv = ((float2*)hdT[r])[lane];
        float p = warpSumAll(hv.x * sAe[2 * lane] + hv.y * sAe[2 * lane + 1]);
        if (lane == 0) sT[r] = p;
    }
    __syncthreads();

    // lane-parallel softmax: threads 0..63, thread = node
    if (t < 64 && nodeBase + t < NN) {
        const int li = 24 + t;
        const float s_i = sT[li];
        float e[25];
#pragma unroll
        for (int tt = 0; tt < 25; tt++) e[tt] = lrelu(sT[li - tt] - s_i);
        float m = e[0];
#pragma unroll
        for (int tt = 1; tt < 25; tt++) m = fmaxf(m, e[tt]);
#pragma unroll
        for (int tt = 0; tt < 25; tt++) e[tt] = __expf(e[tt] - m);
        float p1 = 0.f, p2 = 0.f, p3 = 0.f;
#pragma unroll
        for (int tt = 0; tt < 25; tt++) {
            if (tt < 9)  p1 += e[tt];
            if (tt < 17) p2 += e[tt];
            p3 += e[tt];
        }
        const float r1 = 1.f / p1, r2 = 1.f / p2, r3 = 1.f / p3;
#pragma unroll
        for (int tt = 0; tt < 25; tt++) {
            if (tt < 9)  wS[0][tt][t] = e[tt] * r1;
            if (tt < 17) wS[1][tt][t] = e[tt] * r2;
            wS[2][tt][t] = e[tt] * r3;
        }
    }
    __syncthreads();

    float2 A[8][3];
#pragma unroll
    for (int j = 0; j < 8; j++)
#pragma unroll
        for (int hh = 0; hh < 3; hh++) A[j][hh] = make_float2(0.f, 0.f);

#pragma unroll 1
    for (int tt = 0; tt < 25; tt++) {
        float w3a[8], w2a[8], w1a[8];
        *(float4*)&w3a[0] = *(const float4*)&wS[2][tt][nl0];
        *(float4*)&w3a[4] = *(const float4*)&wS[2][tt][nl0 + 4];
        if (tt < 17) {
            *(float4*)&w2a[0] = *(const float4*)&wS[1][tt][nl0];
            *(float4*)&w2a[4] = *(const float4*)&wS[1][tt][nl0 + 4];
        }
        if (tt < 9) {
            *(float4*)&w1a[0] = *(const float4*)&wS[0][tt][nl0];
            *(float4*)&w1a[4] = *(const float4*)&wS[0][tt][nl0 + 4];
        }
#pragma unroll
        for (int j = 0; j < 8; j++) {
            const float2 hv = ((float2*)hdT[24 + nl0 + j - tt])[lane];
            A[j][2].x = fmaf(w3a[j], hv.x, A[j][2].x);
            A[j][2].y = fmaf(w3a[j], hv.y, A[j][2].y);
            if (tt < 17) {
                A[j][1].x = fmaf(w2a[j], hv.x, A[j][1].x);
                A[j][1].y = fmaf(w2a[j], hv.y, A[j][1].y);
            }
            if (tt < 9) {
                A[j][0].x = fmaf(w1a[j], hv.x, A[j][0].x);
                A[j][0].y = fmaf(w1a[j], hv.y, A[j][0].y);
            }
        }
    }

    const float ac0 = sAc[2 * lane], ac1 = sAc[2 * lane + 1];
#pragma unroll 1
    for (int j = 0; j < 8; j++) {
        const int node = nodeBase + nl0 + j;
        if (node >= NN) break;
        const int li = 24 + nl0 + j;
        const float2 hvi = ((float2*)hdT[li])[lane];
        const float2 zv  = ((const float2*)(g_z1 + node * 64))[lane];
        float2 Z1, Z2, Z3;
        Z1.x = eluf(zv.x + A[j][0].x - hvi.x); Z1.y = eluf(zv.y + A[j][0].y - hvi.y);
        Z2.x = eluf(zv.x + A[j][1].x - hvi.x); Z2.y = eluf(zv.y + A[j][1].y - hvi.y);
        Z3.x = eluf(zv.x + A[j][2].x - hvi.x); Z3.y = eluf(zv.y + A[j][2].y - hvi.y);

        const float c1 = warpSumAll(Z1.x * ac0 + Z1.y * ac1);
        const float c2 = warpSumAll(Z2.x * ac0 + Z2.y * ac1);
        const float c3 = warpSumAll(Z3.x * ac0 + Z3.y * ac1);
        const float l1 = lrelu(c1), l2 = lrelu(c2), l3 = lrelu(c3);
        const float mx = fmaxf(l1, fmaxf(l2, l3));
        const float e1 = __expf(l1 - mx), e2 = __expf(l2 - mx), e3 = __expf(l3 - mx);
        const float rd = 1.f / (e1 + e2 + e3);

        float2 o;
        o.x = (e1 * Z1.x + e2 * Z2.x + e3 * Z3.x) * rd;
        o.y = (e1 * Z1.y + e2 * Z2.y + e3 * Z3.y) * rd;
        ((float2*)(g_zc + node * 64))[lane] = o;
    }
}

// =====================================================================
// decoder aggregation: 64 nodes/block, lane-parallel softmax.
// =====================================================================
__global__ __launch_bounds__(256) void dec_agg(const float* __restrict__ diffD,
                                               const float* __restrict__ attD) {
    __shared__ __align__(16) float zT[88][66];
    __shared__ float sT[88];
    __shared__ __align__(16) float wS[25][72];
    __shared__ float sv[64];

    const int t = threadIdx.x, w = t >> 5, lane = t & 31;
    const int nodeBase = blockIdx.x * 64;
    const int nl0 = w * 8;

    if (t < 64) {
        float a = 0.f;
#pragma unroll 4
        for (int od = 0; od < 128; od++) a = fmaf(diffD[od * 64 + t], attD[od], a);
        sv[t] = a;
    }

    for (int r = w; r < 88; r += 8) {
        int g = nodeBase - 24 + r;
        if (g < 0) g += NN; else if (g >= NN) g -= NN;
        ((float2*)zT[r])[lane] = ((const float2*)(g_zc + g * 64))[lane];
    }
    __syncthreads();

    for (int r = w; r < 88; r += 8) {
        float2 zv = ((float2*)zT[r])[lane];
        float p = warpSumAll(zv.x * sv[2 * lane] + zv.y * sv[2 * lane + 1]);
        if (lane == 0) sT[r] = p;
    }
    __syncthreads();

    if (t < 64 && nodeBase + t < NN) {
        const int li = 24 + t;
        const float s_i = sT[li];
        float e[25];
#pragma unroll
        for (int tt = 0; tt < 25; tt++) e[tt] = lrelu(sT[li - tt] - s_i);
        float m = e[0];
#pragma unroll
        for (int tt = 1; tt < 25; tt++) m = fmaxf(m, e[tt]);
        float p = 0.f;
#pragma unroll
        for (int tt = 0; tt < 25; tt++) { e[tt] = __expf(e[tt] - m); p += e[tt]; }
        const float rd = 1.f / p;
#pragma unroll
        for (int tt = 0; tt < 25; tt++) wS[tt][t] = e[tt] * rd;
    }
    __syncthreads();

    float2 A[8];
#pragma unroll
    for (int j = 0; j < 8; j++) A[j] = make_float2(0.f, 0.f);

#pragma unroll 1
    for (int tt = 0; tt < 25; tt++) {
        float wv[8];
        *(float4*)&wv[0] = *(const float4*)&wS[tt][nl0];
        *(float4*)&wv[4] = *(const float4*)&wS[tt][nl0 + 4];
#pragma unroll
        for (int j = 0; j < 8; j++) {
            const float2 zv = ((float2*)zT[24 + nl0 + j - tt])[lane];
            A[j].x = fmaf(wv[j], zv.x, A[j].x);
            A[j].y = fmaf(wv[j], zv.y, A[j].y);
        }
    }

#pragma unroll 1
    for (int j = 0; j < 8; j++) {
        const int node = nodeBase + nl0 + j;
        if (node >= NN) break;
        const float2 zvi = ((float2*)zT[24 + nl0 + j])[lane];
        float2 o;
        o.x = A[j].x - zvi.x;
        o.y = A[j].y - zvi.y;
        ((float2*)(g_u + node * 64))[lane] = o;
    }
}

// ---------------- launch ----------------
extern "C" void kernel_launch(void* const* d_in, const int* in_sizes, int n_in,
                              void* d_out, int out_size) {
    const float* h        = (const float*)d_in[0];
    const float* fc_enc   = (const float*)d_in[1];
    const float* diff_enc = (const float*)d_in[2];
    const float* att_enc  = (const float*)d_in[3];
    const float* fc_dec   = (const float*)d_in[4];
    const float* diff_dec = (const float*)d_in[5];
    const float* att_dec  = (const float*)d_in[6];
    const float* att_comb = (const float*)d_in[7];
    float* out = (float*)d_out;

    cudaFuncSetAttribute(gemm_f32<0>, cudaFuncAttributeMaxDynamicSharedMemorySize, GSMEM);
    cudaFuncSetAttribute(gemm_f32<1>, cudaFuncAttributeMaxDynamicSharedMemorySize, GSMEM);

    dim3 gemmGrid((NN + MT - 1) / MT, 2);   // (209, 2), one wave @3/SM
    const int aggBlocks = (NN + 63) / 64;   // 313

    gemm_f32<0><<<gemmGrid, NTHR, GSMEM>>>(h, fc_enc, diff_enc, nullptr);
    enc_agg<<<aggBlocks, 256>>>(att_enc, att_comb);
    dec_agg<<<aggBlocks, 256>>>(diff_dec, att_dec);
    gemm_f32<1><<<gemmGrid, NTHR, GSMEM>>>(nullptr, fc_dec, diff_dec, out);
}